// round 2
// baseline (speedup 1.0000x reference)
#include <cuda_runtime.h>
#include <math.h>

#define BSZ  8
#define SEQ  2048
#define DM   512
#define DAUX 64
#define NEG_HUGE (-3.402823466e38f)

// Static scratch (no allocation allowed in kernel_launch)
__device__ float g_q[(size_t)BSZ*SEQ*DM];
__device__ float g_k[(size_t)BSZ*SEQ*DM];
__device__ float g_v[(size_t)BSZ*SEQ*DM];
__device__ float g_s[(size_t)BSZ*SEQ*SEQ];

// ---------------------------------------------------------------------------
// QKV projection: out[m,n] = sum_k x[m,k] * W[n,k] + bias[n]
// (A @ B^T with both row-major). 64x64 tile, K-chunk 16, 256 thr, 4x4 micro.
// grid: (DM/64, (BSZ*SEQ)/64, 3)   z selects q/k/v
// ---------------------------------------------------------------------------
__global__ __launch_bounds__(256) void qkv_kernel(
    const float* __restrict__ x,
    const float* __restrict__ Wq, const float* __restrict__ bq,
    const float* __restrict__ Wk, const float* __restrict__ bk,
    const float* __restrict__ Wv, const float* __restrict__ bv)
{
    const float* W; const float* bias; float* out;
    if (blockIdx.z == 0)      { W = Wq; bias = bq; out = g_q; }
    else if (blockIdx.z == 1) { W = Wk; bias = bk; out = g_k; }
    else                      { W = Wv; bias = bv; out = g_v; }

    const int m0 = blockIdx.y * 64;
    const int n0 = blockIdx.x * 64;

    __shared__ float As[16][65];   // As[k][m]
    __shared__ float Bs[16][65];   // Bs[k][n]

    const int tid = threadIdx.x;
    const int tx = tid & 15, ty = tid >> 4;
    const int lr = tid >> 4, lc = tid & 15;

    float acc[4][4] = {};

    for (int k0 = 0; k0 < DM; k0 += 16) {
        #pragma unroll
        for (int i = 0; i < 4; i++) {
            int r = lr + i*16;
            As[lc][r] = x[(size_t)(m0 + r)*DM + k0 + lc];
            Bs[lc][r] = W[(size_t)(n0 + r)*DM + k0 + lc];
        }
        __syncthreads();
        #pragma unroll
        for (int kk = 0; kk < 16; kk++) {
            float a[4], b[4];
            #pragma unroll
            for (int i = 0; i < 4; i++) a[i] = As[kk][ty + i*16];
            #pragma unroll
            for (int j = 0; j < 4; j++) b[j] = Bs[kk][tx + j*16];
            #pragma unroll
            for (int i = 0; i < 4; i++)
                #pragma unroll
                for (int j = 0; j < 4; j++)
                    acc[i][j] += a[i]*b[j];
        }
        __syncthreads();
    }

    #pragma unroll
    for (int i = 0; i < 4; i++) {
        int m = m0 + ty + i*16;
        #pragma unroll
        for (int j = 0; j < 4; j++) {
            int n = n0 + tx + j*16;
            out[(size_t)m*DM + n] = acc[i][j] + bias[n];
        }
    }
}

// ---------------------------------------------------------------------------
// scores[b,n,m] = merge(q.k^T/sqrt(D), qa.ka^T/sqrt(Daux)) with adjacency mask
// grid: (SEQ/64 key tiles, SEQ/64 query tiles, BSZ)
// ---------------------------------------------------------------------------
__global__ __launch_bounds__(256) void scores_kernel(
    const float* __restrict__ qa, const float* __restrict__ ka,
    const int*   __restrict__ adj,
    const float* __restrict__ p_mc, const float* __restrict__ p_thr)
{
    const int b  = blockIdx.z;
    const int n0 = blockIdx.y * 64;   // query rows
    const int m0 = blockIdx.x * 64;   // key rows

    const float* Q  = g_q + (size_t)b*SEQ*DM;
    const float* K  = g_k + (size_t)b*SEQ*DM;
    const float* QA = qa  + (size_t)b*SEQ*DAUX;
    const float* KA = ka  + (size_t)b*SEQ*DAUX;

    __shared__ float As[16][65];
    __shared__ float Bs[16][65];

    const int tid = threadIdx.x;
    const int tx = tid & 15, ty = tid >> 4;
    const int lr = tid >> 4, lc = tid & 15;

    float acc[4][4] = {};
    for (int k0 = 0; k0 < DM; k0 += 16) {
        #pragma unroll
        for (int i = 0; i < 4; i++) {
            int r = lr + i*16;
            As[lc][r] = Q[(size_t)(n0 + r)*DM + k0 + lc];
            Bs[lc][r] = K[(size_t)(m0 + r)*DM + k0 + lc];
        }
        __syncthreads();
        #pragma unroll
        for (int kk = 0; kk < 16; kk++) {
            float a[4], bb[4];
            #pragma unroll
            for (int i = 0; i < 4; i++) a[i] = As[kk][ty + i*16];
            #pragma unroll
            for (int j = 0; j < 4; j++) bb[j] = Bs[kk][tx + j*16];
            #pragma unroll
            for (int i = 0; i < 4; i++)
                #pragma unroll
                for (int j = 0; j < 4; j++)
                    acc[i][j] += a[i]*bb[j];
        }
        __syncthreads();
    }

    float accaux[4][4] = {};
    for (int k0 = 0; k0 < DAUX; k0 += 16) {
        #pragma unroll
        for (int i = 0; i < 4; i++) {
            int r = lr + i*16;
            As[lc][r] = QA[(size_t)(n0 + r)*DAUX + k0 + lc];
            Bs[lc][r] = KA[(size_t)(m0 + r)*DAUX + k0 + lc];
        }
        __syncthreads();
        #pragma unroll
        for (int kk = 0; kk < 16; kk++) {
            float a[4], bb[4];
            #pragma unroll
            for (int i = 0; i < 4; i++) a[i] = As[kk][ty + i*16];
            #pragma unroll
            for (int j = 0; j < 4; j++) bb[j] = Bs[kk][tx + j*16];
            #pragma unroll
            for (int i = 0; i < 4; i++)
                #pragma unroll
                for (int j = 0; j < 4; j++)
                    accaux[i][j] += a[i]*bb[j];
        }
        __syncthreads();
    }

    const float mc  = *p_mc;
    const float thr = *p_thr;
    const float inv_s    = 1.0f / sqrtf((float)DM);
    const float inv_saux = 1.0f / sqrtf((float)DAUX);

    #pragma unroll
    for (int i = 0; i < 4; i++) {
        int n = n0 + ty + i*16;
        #pragma unroll
        for (int j = 0; j < 4; j++) {
            int m = m0 + tx + j*16;
            float s  = acc[i][j]    * inv_s;
            float sa = accaux[i][j] * inv_saux;
            if ((sa != 0.0f) && (s > thr))
                s = (1.0f - mc)*s + mc*sa;
            size_t idx = ((size_t)b*SEQ + n)*SEQ + m;
            if (adj[idx] == 0) s = NEG_HUGE;
            g_s[idx] = s;
        }
    }
}

// ---------------------------------------------------------------------------
// Row softmax over g_s rows (length SEQ). One CTA (256 thr) per row.
// ---------------------------------------------------------------------------
__global__ __launch_bounds__(256) void softmax_kernel()
{
    const size_t row = blockIdx.x;
    float* s = g_s + row * SEQ;
    const int tid = threadIdx.x;

    float v[8];
    float mx = -INFINITY;
    #pragma unroll
    for (int i = 0; i < 8; i++) {
        v[i] = s[tid + i*256];
        mx = fmaxf(mx, v[i]);
    }

    __shared__ float red[8];
    // block max
    #pragma unroll
    for (int o = 16; o; o >>= 1) mx = fmaxf(mx, __shfl_xor_sync(0xffffffffu, mx, o));
    if ((tid & 31) == 0) red[tid >> 5] = mx;
    __syncthreads();
    if (tid < 32) {
        float t = (tid < 8) ? red[tid] : -INFINITY;
        #pragma unroll
        for (int o = 4; o; o >>= 1) t = fmaxf(t, __shfl_xor_sync(0xffffffffu, t, o));
        if (tid == 0) red[0] = t;
    }
    __syncthreads();
    mx = red[0];
    __syncthreads();

    float sum = 0.0f;
    #pragma unroll
    for (int i = 0; i < 8; i++) {
        v[i] = expf(v[i] - mx);
        sum += v[i];
    }
    // block sum
    #pragma unroll
    for (int o = 16; o; o >>= 1) sum += __shfl_xor_sync(0xffffffffu, sum, o);
    if ((tid & 31) == 0) red[tid >> 5] = sum;
    __syncthreads();
    if (tid < 32) {
        float t = (tid < 8) ? red[tid] : 0.0f;
        #pragma unroll
        for (int o = 4; o; o >>= 1) t += __shfl_xor_sync(0xffffffffu, t, o);
        if (tid == 0) red[0] = t;
    }
    __syncthreads();
    const float inv = 1.0f / red[0];

    #pragma unroll
    for (int i = 0; i < 8; i++)
        s[tid + i*256] = v[i] * inv;
}

// ---------------------------------------------------------------------------
// out[b,n,d] = sum_m weights[b,n,m] * v[b,m,d]   (A @ B, both row-major)
// grid: (DM/64, SEQ/64, BSZ)
// ---------------------------------------------------------------------------
__global__ __launch_bounds__(256) void av_kernel(float* __restrict__ out)
{
    const int b  = blockIdx.z;
    const int n0 = blockIdx.y * 64;
    const int d0 = blockIdx.x * 64;

    const float* Wt = g_s + (size_t)b*SEQ*SEQ;
    const float* V  = g_v + (size_t)b*SEQ*DM;

    __shared__ float As[16][65];   // As[k][row]
    __shared__ float Bs[16][65];   // Bs[k][col]

    const int tid = threadIdx.x;
    const int tx = tid & 15, ty = tid >> 4;
    const int lr = tid >> 4, lc = tid & 15;
    const int bc = tid & 63;   // col 0..63
    const int bk = tid >> 6;   // 0..3

    float acc[4][4] = {};

    for (int k0 = 0; k0 < SEQ; k0 += 16) {
        #pragma unroll
        for (int i = 0; i < 4; i++)
            As[lc][lr + i*16] = Wt[(size_t)(n0 + lr + i*16)*SEQ + k0 + lc];
        #pragma unroll
        for (int i = 0; i < 4; i++)
            Bs[bk + i*4][bc] = V[(size_t)(k0 + bk + i*4)*DM + d0 + bc];
        __syncthreads();
        #pragma unroll
        for (int kk = 0; kk < 16; kk++) {
            float a[4], bb[4];
            #pragma unroll
            for (int i = 0; i < 4; i++) a[i] = As[kk][ty + i*16];
            #pragma unroll
            for (int j = 0; j < 4; j++) bb[j] = Bs[kk][tx + j*16];
            #pragma unroll
            for (int i = 0; i < 4; i++)
                #pragma unroll
                for (int j = 0; j < 4; j++)
                    acc[i][j] += a[i]*bb[j];
        }
        __syncthreads();
    }

    #pragma unroll
    for (int i = 0; i < 4; i++) {
        int n = n0 + ty + i*16;
        #pragma unroll
        for (int j = 0; j < 4; j++) {
            int d = d0 + tx + j*16;
            out[((size_t)b*SEQ + n)*DM + d] = acc[i][j];
        }
    }
}

// ---------------------------------------------------------------------------
extern "C" void kernel_launch(void* const* d_in, const int* in_sizes, int n_in,
                              void* d_out, int out_size)
{
    const float* x   = (const float*)d_in[0];
    const float* qa  = (const float*)d_in[1];
    const float* ka  = (const float*)d_in[2];
    const int*   adj = (const int*)d_in[3];
    const float* mc  = (const float*)d_in[4];
    const float* Wq  = (const float*)d_in[5];
    const float* bq  = (const float*)d_in[6];
    const float* Wk  = (const float*)d_in[7];
    const float* bk  = (const float*)d_in[8];
    const float* Wv  = (const float*)d_in[9];
    const float* bv  = (const float*)d_in[10];
    const float* thr = (const float*)d_in[11];
    float* out = (float*)d_out;

    dim3 t(256);
    qkv_kernel   <<<dim3(DM/64, (BSZ*SEQ)/64, 3),  t>>>(x, Wq, bq, Wk, bk, Wv, bv);
    scores_kernel<<<dim3(SEQ/64, SEQ/64, BSZ),     t>>>(qa, ka, adj, mc, thr);
    softmax_kernel<<<dim3(BSZ*SEQ),                t>>>();
    av_kernel    <<<dim3(DM/64, SEQ/64, BSZ),      t>>>(out);
}